// round 5
// baseline (speedup 1.0000x reference)
#include <cuda_runtime.h>
#include <cstdint>

// Problem constants
#define A_CLS 50
#define C_CL  1024
#define F_LIT 1180
#define B_SMP 512
#define NW    37                 // ceil(1180/32) words per bitmask
#define AC    (A_CLS * C_CL)     // 51200 clauses total
#define BCHUNK 64                // samples per eval block

// Scratch (static __device__ globals — no runtime allocation)
__device__ unsigned d_maskPos[NW][AC];   // word-major: word w for all (a,c) contiguous
__device__ unsigned d_maskNeg[NW][AC];
__device__ unsigned d_xbits[B_SMP][NW];
__device__ float    d_votes[B_SMP * A_CLS];

// ---------------------------------------------------------------------------
// Pack binary_features [B, F] -> bitmasks (bit set iff x == 1)
// ---------------------------------------------------------------------------
__global__ void pack_x_kernel(const float* __restrict__ x) {
    int warp = (blockIdx.x * blockDim.x + threadIdx.x) >> 5;
    int lane = threadIdx.x & 31;
    if (warp >= B_SMP) return;
    const float* row = x + (size_t)warp * F_LIT;
    #pragma unroll
    for (int w = 0; w < NW; w++) {
        int f = w * 32 + lane;
        bool on = (f < F_LIT) && (row[f] > 0.5f);
        unsigned bits = __ballot_sync(0xFFFFFFFFu, on);
        if (lane == 0) d_xbits[warp][w] = bits;
    }
}

// ---------------------------------------------------------------------------
// Pack ta_state [A, C, 2, F] -> included-literal bitmasks (state > 16)
// One warp per (a, c, pol) row; fully coalesced 32b loads; ballot pack.
// ---------------------------------------------------------------------------
__global__ void pack_ta_kernel(const float* __restrict__ ta) {
    int warp = (blockIdx.x * blockDim.x + threadIdx.x) >> 5;
    int lane = threadIdx.x & 31;
    if (warp >= AC * 2) return;
    int ac  = warp >> 1;
    int pol = warp & 1;
    const float* row = ta + (size_t)warp * F_LIT;
    #pragma unroll
    for (int w = 0; w < NW; w++) {
        int f = w * 32 + lane;
        bool inc = (f < F_LIT) && (row[f] > 16.0f);
        unsigned bits = __ballot_sync(0xFFFFFFFFu, inc);
        if (lane == 0) {
            if (pol == 0) d_maskPos[w][ac] = bits;
            else          d_maskNeg[w][ac] = bits;
        }
    }
}

// ---------------------------------------------------------------------------
// Zero the vote accumulator (d_out is poisoned; votes must start at 0)
// ---------------------------------------------------------------------------
__global__ void zero_votes_kernel() {
    int i = blockIdx.x * blockDim.x + threadIdx.x;
    if (i < B_SMP * A_CLS) d_votes[i] = 0.0f;
}

// ---------------------------------------------------------------------------
// Clause evaluation: block = (a, b-chunk), thread = clause c.
// Word-0 masks live in registers; x bits for the b-chunk live in smem.
// Clause fires iff (pos & ~x) | (neg & x) == 0 across all 37 words.
// Early-exit on word 0 covers ~(1 - 1e-8) of evaluations for this data.
// ---------------------------------------------------------------------------
__global__ __launch_bounds__(1024, 2)
void eval_kernel(const float* __restrict__ clause_sign) {
    __shared__ unsigned sx[BCHUNK * NW];

    int a  = blockIdx.x;
    int b0 = blockIdx.y * BCHUNK;

    // cooperative load of this chunk's x bitmasks into smem
    for (int i = threadIdx.x; i < BCHUNK * NW; i += 1024) {
        sx[i] = d_xbits[b0 + i / NW][i % NW];
    }
    __syncthreads();

    int c   = threadIdx.x;
    int idx = a * C_CL + c;
    unsigned p0 = d_maskPos[0][idx];
    unsigned n0 = d_maskNeg[0][idx];
    float    sg = clause_sign[idx];

    #pragma unroll 4
    for (int bl = 0; bl < BCHUNK; bl++) {
        unsigned x0 = sx[bl * NW];                       // broadcast LDS
        unsigned v  = (p0 & ~x0) | (n0 & x0);            // 2 LOP3
        if (v == 0u) {                                   // rare path
            #pragma unroll 1
            for (int w = 1; w < NW && v == 0u; w++) {
                unsigned x = sx[bl * NW + w];
                v = (d_maskPos[w][idx] & ~x) | (d_maskNeg[w][idx] & x);
            }
            if (v == 0u)
                atomicAdd(&d_votes[(b0 + bl) * A_CLS + a], sg);
        }
    }
}

// ---------------------------------------------------------------------------
// Epilogue: clip votes to [-T, T] and write output [B, A].
// T arrives as a 1-element buffer of ambiguous dtype (python int in the
// reference): small non-negative int bit-patterns are taken as int32,
// anything else as float32 bits.
// ---------------------------------------------------------------------------
__global__ void finish_kernel(float* __restrict__ out, const int* __restrict__ tptr) {
    int i = blockIdx.x * blockDim.x + threadIdx.x;
    if (i >= B_SMP * A_CLS) return;
    int ti = *tptr;
    float T = (ti >= 0 && ti < (1 << 23)) ? (float)ti : __int_as_float(ti);
    float v = d_votes[i];
    out[i] = fminf(fmaxf(v, -T), T);
}

// ---------------------------------------------------------------------------
extern "C" void kernel_launch(void* const* d_in, const int* in_sizes, int n_in,
                              void* d_out, int out_size) {
    const float* x  = (const float*)d_in[0];  // binary_features [512, 1180]
    const float* ta = (const float*)d_in[1];  // ta_state [50, 1024, 2, 1180]
    const float* cs = (const float*)d_in[2];  // clause_sign [50, 1024]
    const int*   Tp = (const int*)  d_in[3];  // T scalar

    (void)in_sizes; (void)n_in; (void)out_size;

    // 1. pack features: 512 warps
    {
        int threads = B_SMP * 32;
        pack_x_kernel<<<(threads + 255) / 256, 256>>>(x);
    }
    // 2. pack TA states: 102400 warps (DRAM-bound, 483 MB)
    {
        long long threads = (long long)AC * 2 * 32;
        pack_ta_kernel<<<(int)((threads + 255) / 256), 256>>>(ta);
    }
    // 3. zero vote accumulator
    zero_votes_kernel<<<(B_SMP * A_CLS + 255) / 256, 256>>>();
    // 4. evaluate clauses: grid (A, B/BCHUNK), 1 thread per clause
    {
        dim3 grid(A_CLS, B_SMP / BCHUNK);
        eval_kernel<<<grid, 1024>>>(cs);
    }
    // 5. clip + write output
    finish_kernel<<<(B_SMP * A_CLS + 255) / 256, 256>>>((float*)d_out, Tp);
}

// round 6
// speedup vs baseline: 1.1156x; 1.1156x over previous
#include <cuda_runtime.h>
#include <cstdint>

// Problem constants
#define A_CLS 50
#define C_CL  1024
#define F_LIT 1180
#define B_SMP 512
#define NW2   40                 // 10 float4-iterations x 4 ballot-words
#define AC    (A_CLS * C_CL)     // 51200 clauses
#define BCHUNK 64                // samples per eval block

// Scratch (static __device__ globals — no runtime allocation)
// Bit order: iteration i covers literals [i*128, i*128+128); lane l's float4 is
// literals i*128+l*4 .. +3; word (4i+j) = ballot over lanes of component j.
// The SAME permutation is used for x and ta masks, so violation logic is exact.
__device__ unsigned d_maskPos[NW2][AC];   // word-major
__device__ unsigned d_maskNeg[NW2][AC];
__device__ unsigned d_xbits[B_SMP][NW2];  // row-major per sample
__device__ float    d_votes[B_SMP * A_CLS];

// ---------------------------------------------------------------------------
// Pack binary_features [B, F] -> x bitmasks; also zero the vote accumulator.
// One warp per sample row; float4 loads (rows are 16B-aligned: 1180*4 = 4720).
// ---------------------------------------------------------------------------
__global__ void pack_x_kernel(const float* __restrict__ x) {
    int gtid = blockIdx.x * blockDim.x + threadIdx.x;
    int warp = gtid >> 5;
    int lane = threadIdx.x & 31;
    if (warp < B_SMP) {
        const float4* row4 = reinterpret_cast<const float4*>(x + (size_t)warp * F_LIT);
        #pragma unroll
        for (int i = 0; i < 10; i++) {
            int base = i * 128 + lane * 4;
            float4 v = make_float4(0.f, 0.f, 0.f, 0.f);
            if (base < F_LIT) v = __ldg(&row4[i * 32 + lane]);
            unsigned b0 = __ballot_sync(0xFFFFFFFFu, v.x > 0.5f);
            unsigned b1 = __ballot_sync(0xFFFFFFFFu, v.y > 0.5f);
            unsigned b2 = __ballot_sync(0xFFFFFFFFu, v.z > 0.5f);
            unsigned b3 = __ballot_sync(0xFFFFFFFFu, v.w > 0.5f);
            if (lane == 0) {
                d_xbits[warp][i * 4 + 0] = b0;
                d_xbits[warp][i * 4 + 1] = b1;
                d_xbits[warp][i * 4 + 2] = b2;
                d_xbits[warp][i * 4 + 3] = b3;
            }
        }
    }
    // fused vote zeroing (same stream ordering guarantees this precedes eval)
    for (int i = gtid; i < B_SMP * A_CLS; i += gridDim.x * blockDim.x)
        d_votes[i] = 0.0f;
}

// ---------------------------------------------------------------------------
// Pack ta_state [A, C, 2, F] -> included-literal masks (state > 16).
// One warp per (a, c, pol) row; LDG.128 coalesced; DRAM-bound (483 MB).
// ---------------------------------------------------------------------------
__global__ void pack_ta_kernel(const float* __restrict__ ta) {
    int warp = (blockIdx.x * blockDim.x + threadIdx.x) >> 5;
    int lane = threadIdx.x & 31;
    if (warp >= AC * 2) return;
    int ac  = warp >> 1;
    int pol = warp & 1;
    const float4* row4 = reinterpret_cast<const float4*>(ta + (size_t)warp * F_LIT);
    unsigned* dstBase = pol ? &d_maskNeg[0][ac] : &d_maskPos[0][ac];
    #pragma unroll
    for (int i = 0; i < 10; i++) {
        int base = i * 128 + lane * 4;
        float4 v = make_float4(0.f, 0.f, 0.f, 0.f);
        if (base < F_LIT) v = __ldg(&row4[i * 32 + lane]);
        unsigned b0 = __ballot_sync(0xFFFFFFFFu, v.x > 16.0f);
        unsigned b1 = __ballot_sync(0xFFFFFFFFu, v.y > 16.0f);
        unsigned b2 = __ballot_sync(0xFFFFFFFFu, v.z > 16.0f);
        unsigned b3 = __ballot_sync(0xFFFFFFFFu, v.w > 16.0f);
        if (lane == 0) {
            unsigned* dst = dstBase + (size_t)(i * 4) * AC;
            dst[0]              = b0;
            dst[(size_t)AC]     = b1;
            dst[(size_t)2 * AC] = b2;
            dst[(size_t)3 * AC] = b3;
        }
    }
}

// ---------------------------------------------------------------------------
// Clause evaluation: block = (a, b-chunk), thread = clause c.
// Word-0 masks in registers; word-0 x values in smem, read 4-at-a-time via
// LDS.128. P(word-0 clean) ~ 0.5^32, so the full 40-word check + atomicAdd
// almost never runs — it reads straight from global (L2-hot).
// ---------------------------------------------------------------------------
__global__ __launch_bounds__(1024, 2)
void eval_kernel(const float* __restrict__ clause_sign) {
    __shared__ __align__(16) unsigned sx0[BCHUNK];

    int a  = blockIdx.x;
    int b0 = blockIdx.y * BCHUNK;

    if (threadIdx.x < BCHUNK)
        sx0[threadIdx.x] = d_xbits[b0 + threadIdx.x][0];
    __syncthreads();

    int c   = threadIdx.x;
    int idx = a * C_CL + c;
    unsigned p0 = d_maskPos[0][idx];
    unsigned n0 = d_maskNeg[0][idx];
    float    sg = clause_sign[idx];

    #pragma unroll
    for (int bl = 0; bl < BCHUNK; bl += 4) {
        uint4 x = *reinterpret_cast<const uint4*>(&sx0[bl]);
        unsigned v0 = (p0 & ~x.x) | (n0 & x.x);
        unsigned v1 = (p0 & ~x.y) | (n0 & x.y);
        unsigned v2 = (p0 & ~x.z) | (n0 & x.z);
        unsigned v3 = (p0 & ~x.w) | (n0 & x.w);
        unsigned m  = min(min(v0, v1), min(v2, v3));
        if (m == 0u) {                       // rare (~2e-10 per eval)
            unsigned vv[4] = {v0, v1, v2, v3};
            #pragma unroll 1
            for (int j = 0; j < 4; j++) {
                if (vv[j] != 0u) continue;
                int b = b0 + bl + j;
                bool fire = true;
                #pragma unroll 1
                for (int w = 1; w < NW2 && fire; w++) {
                    unsigned xx = d_xbits[b][w];
                    unsigned vw = (d_maskPos[w][idx] & ~xx) | (d_maskNeg[w][idx] & xx);
                    if (vw) fire = false;
                }
                if (fire)
                    atomicAdd(&d_votes[b * A_CLS + a], sg);
            }
        }
    }
}

// ---------------------------------------------------------------------------
// Epilogue: clip votes to [-T, T]. T dtype is ambiguous (python int in the
// reference); small non-negative int bit-patterns -> int32, else float bits.
// ---------------------------------------------------------------------------
__global__ void finish_kernel(float* __restrict__ out, const int* __restrict__ tptr) {
    int i = blockIdx.x * blockDim.x + threadIdx.x;
    if (i >= B_SMP * A_CLS) return;
    int ti = *tptr;
    float T = (ti >= 0 && ti < (1 << 23)) ? (float)ti : __int_as_float(ti);
    float v = d_votes[i];
    out[i] = fminf(fmaxf(v, -T), T);
}

// ---------------------------------------------------------------------------
extern "C" void kernel_launch(void* const* d_in, const int* in_sizes, int n_in,
                              void* d_out, int out_size) {
    const float* x  = (const float*)d_in[0];  // binary_features [512, 1180]
    const float* ta = (const float*)d_in[1];  // ta_state [50, 1024, 2, 1180]
    const float* cs = (const float*)d_in[2];  // clause_sign [50, 1024]
    const int*   Tp = (const int*)  d_in[3];  // T scalar

    (void)in_sizes; (void)n_in; (void)out_size;

    // 1. pack features (512 warps) + zero votes
    pack_x_kernel<<<64, 256>>>(x);
    // 2. pack TA states: 102400 warps, 483 MB read — DRAM-bound
    {
        long long threads = (long long)AC * 2 * 32;
        pack_ta_kernel<<<(int)((threads + 255) / 256), 256>>>(ta);
    }
    // 3. evaluate clauses: grid (A, B/BCHUNK), thread = clause
    {
        dim3 grid(A_CLS, B_SMP / BCHUNK);
        eval_kernel<<<grid, 1024>>>(cs);
    }
    // 4. clip + write output
    finish_kernel<<<(B_SMP * A_CLS + 255) / 256, 256>>>((float*)d_out, Tp);
}

// round 7
// speedup vs baseline: 1.1484x; 1.0294x over previous
#include <cuda_runtime.h>
#include <cstdint>

// Problem constants
#define A_CLS 50
#define C_CL  1024
#define F_LIT 1180
#define B_SMP 512
#define NW2   40                 // 10 float4-iterations x 4 ballot-words
#define AC    (A_CLS * C_CL)     // 51200 clauses
#define BCHUNK 64                // samples per eval block

// Scratch (static __device__ globals — no runtime allocation)
// Bit order: iteration i covers literals [i*128, i*128+128); lane l's float4
// holds literals i*128+l*4 .. +3; ballot word j of iteration i packs component
// j across lanes. Identical permutation for x and ta masks -> logic is exact.
// Layout: masks[i][ac] is a uint4 = words (4i..4i+3) for clause ac (STG.128).
__device__ uint4 d_maskPos[10][AC];
__device__ uint4 d_maskNeg[10][AC];
__device__ uint4 d_xbits[B_SMP][10];

// ---------------------------------------------------------------------------
// Fused pack: warps [0, AC*2) threshold+pack ta_state rows (483 MB, DRAM-
// bound); warps [AC*2, AC*2+512) pack the feature rows. One launch.
// ---------------------------------------------------------------------------
__global__ void pack_kernel(const float* __restrict__ ta,
                            const float* __restrict__ x) {
    int warp = (blockIdx.x * blockDim.x + threadIdx.x) >> 5;
    int lane = threadIdx.x & 31;

    if (warp < AC * 2) {
        int ac  = warp >> 1;
        int pol = warp & 1;
        const float4* row4 = reinterpret_cast<const float4*>(ta + (size_t)warp * F_LIT);
        uint4* dst = pol ? &d_maskNeg[0][ac] : &d_maskPos[0][ac];
        #pragma unroll
        for (int i = 0; i < 10; i++) {
            float4 v = make_float4(0.f, 0.f, 0.f, 0.f);
            if (i * 128 + lane * 4 < F_LIT) v = __ldg(&row4[i * 32 + lane]);
            unsigned b0 = __ballot_sync(0xFFFFFFFFu, v.x > 16.0f);
            unsigned b1 = __ballot_sync(0xFFFFFFFFu, v.y > 16.0f);
            unsigned b2 = __ballot_sync(0xFFFFFFFFu, v.z > 16.0f);
            unsigned b3 = __ballot_sync(0xFFFFFFFFu, v.w > 16.0f);
            if (lane == 0) dst[(size_t)i * AC] = make_uint4(b0, b1, b2, b3);
        }
    } else if (warp < AC * 2 + B_SMP) {
        int b = warp - AC * 2;
        const float4* row4 = reinterpret_cast<const float4*>(x + (size_t)b * F_LIT);
        #pragma unroll
        for (int i = 0; i < 10; i++) {
            float4 v = make_float4(0.f, 0.f, 0.f, 0.f);
            if (i * 128 + lane * 4 < F_LIT) v = __ldg(&row4[i * 32 + lane]);
            unsigned b0 = __ballot_sync(0xFFFFFFFFu, v.x > 0.5f);
            unsigned b1 = __ballot_sync(0xFFFFFFFFu, v.y > 0.5f);
            unsigned b2 = __ballot_sync(0xFFFFFFFFu, v.z > 0.5f);
            unsigned b3 = __ballot_sync(0xFFFFFFFFu, v.w > 0.5f);
            if (lane == 0) d_xbits[b][i] = make_uint4(b0, b1, b2, b3);
        }
    }
}

// ---------------------------------------------------------------------------
// Clause eval + vote + clip, fully fused. Block (a, y) exclusively owns
// out[b, a] for its 64 samples: votes accumulate in SMEM, clipped output is
// written directly — no global vote buffer, no zeroing pass, no epilogue.
// Fast path: word-0 masks in registers, 4 samples per LDS.128, one compare.
// Slow path (P ~ 0.5^32 per eval with random data) checks all 40 words from
// global (L2-hot) and atomicAdd's the clause sign into the SMEM vote.
// ---------------------------------------------------------------------------
__global__ __launch_bounds__(1024, 2)
void eval_kernel(const float* __restrict__ clause_sign,
                 const int*   __restrict__ tptr,
                 float*       __restrict__ out) {
    __shared__ __align__(16) unsigned sx0[BCHUNK];
    __shared__ float sv[BCHUNK];

    int a  = blockIdx.x;
    int b0 = blockIdx.y * BCHUNK;

    if (threadIdx.x < BCHUNK) {
        sx0[threadIdx.x] = d_xbits[b0 + threadIdx.x][0].x;   // word 0
        sv[threadIdx.x]  = 0.0f;
    }
    __syncthreads();

    int idx = a * C_CL + threadIdx.x;
    unsigned p0 = d_maskPos[0][idx].x;
    unsigned n0 = d_maskNeg[0][idx].x;
    float    sg = clause_sign[idx];

    #pragma unroll
    for (int bl = 0; bl < BCHUNK; bl += 4) {
        uint4 x = *reinterpret_cast<const uint4*>(&sx0[bl]);
        unsigned v0 = (p0 & ~x.x) | (n0 & x.x);
        unsigned v1 = (p0 & ~x.y) | (n0 & x.y);
        unsigned v2 = (p0 & ~x.z) | (n0 & x.z);
        unsigned v3 = (p0 & ~x.w) | (n0 & x.w);
        unsigned m  = min(min(v0, v1), min(v2, v3));
        if (m == 0u) {                              // rare path
            unsigned vv[4] = {v0, v1, v2, v3};
            #pragma unroll 1
            for (int j = 0; j < 4; j++) {
                if (vv[j] != 0u) continue;
                int b = b0 + bl + j;
                const unsigned* xr = reinterpret_cast<const unsigned*>(&d_xbits[b][0]);
                bool fire = true;
                #pragma unroll 1
                for (int w = 1; w < NW2 && fire; w++) {
                    unsigned xx = xr[w];
                    unsigned pw = reinterpret_cast<const unsigned*>(&d_maskPos[w >> 2][idx])[w & 3];
                    unsigned nw = reinterpret_cast<const unsigned*>(&d_maskNeg[w >> 2][idx])[w & 3];
                    if ((pw & ~xx) | (nw & xx)) fire = false;
                }
                if (fire) atomicAdd(&sv[bl + j], sg);
            }
        }
    }
    __syncthreads();

    if (threadIdx.x < BCHUNK) {
        // T's dtype is ambiguous (python int in the reference): small
        // non-negative bit-patterns -> int32, anything else -> float32 bits.
        int ti = *tptr;
        float T = (ti >= 0 && ti < (1 << 23)) ? (float)ti : __int_as_float(ti);
        float v = sv[threadIdx.x];
        out[(b0 + threadIdx.x) * A_CLS + a] = fminf(fmaxf(v, -T), T);
    }
}

// ---------------------------------------------------------------------------
extern "C" void kernel_launch(void* const* d_in, const int* in_sizes, int n_in,
                              void* d_out, int out_size) {
    const float* x  = (const float*)d_in[0];  // binary_features [512, 1180]
    const float* ta = (const float*)d_in[1];  // ta_state [50, 1024, 2, 1180]
    const float* cs = (const float*)d_in[2];  // clause_sign [50, 1024]
    const int*   Tp = (const int*)  d_in[3];  // T scalar

    (void)in_sizes; (void)n_in; (void)out_size;

    // 1. fused pack (ta masks + x bits): 102912 warps, DRAM-bound on 483 MB
    {
        long long warps = (long long)AC * 2 + B_SMP;
        long long threads = warps * 32;
        pack_kernel<<<(int)((threads + 255) / 256), 256>>>(ta, x);
    }
    // 2. fused eval + vote + clip: grid (A, B/BCHUNK), thread = clause
    {
        dim3 grid(A_CLS, B_SMP / BCHUNK);
        eval_kernel<<<grid, 1024>>>(cs, Tp, (float*)d_out);
    }
}